// round 11
// baseline (speedup 1.0000x reference)
#include <cuda_runtime.h>
#include <cuda_fp16.h>
#include <cstdint>

#define EPSV 1e-5f
#define QSCALE (0.0625f * 1.44269504088896340736f)   // 1/sqrt(256) * log2(e)

// ---------------- scratch ----------------
__device__ __half g_Wh[768 * 256];           // BN+scale folded QKV weight (fp16)
__device__ float  g_bp[768];                 // folded QKV bias (fp32, Q rows scaled)
__device__ __half g_Woh[256 * 256];          // out_w fp16
__device__ __half g_qkvh[16 * 768 * 1024];   // [b][o][p] fp16
__device__ __half g_avh[16 * 256 * 1024];    // [b][c][p] fp16

// ---------------- helpers ----------------
__device__ __forceinline__ void mma_f16(float c[4], const unsigned a[4],
                                        unsigned b0, unsigned b1) {
    asm volatile("mma.sync.aligned.m16n8k16.row.col.f32.f16.f16.f32 "
                 "{%0,%1,%2,%3}, {%4,%5,%6,%7}, {%8,%9}, {%0,%1,%2,%3};"
                 : "+f"(c[0]), "+f"(c[1]), "+f"(c[2]), "+f"(c[3])
                 : "r"(a[0]), "r"(a[1]), "r"(a[2]), "r"(a[3]), "r"(b0), "r"(b1));
}
__device__ __forceinline__ unsigned packh2(float lo, float hi) {
    unsigned d; asm("cvt.rn.f16x2.f32 %0, %1, %2;" : "=r"(d) : "f"(hi), "f"(lo)); return d;
}
__device__ __forceinline__ unsigned h2exp2(unsigned x) {
    unsigned r; asm("ex2.approx.f16x2 %0, %1;" : "=r"(r) : "r"(x)); return r;
}
__device__ __forceinline__ unsigned h2add(unsigned a, unsigned b) {
    unsigned r; asm("add.f16x2 %0, %1, %2;" : "=r"(r) : "r"(a), "r"(b)); return r;
}
__device__ __forceinline__ void cp16(uint32_t dst, const void* src) {
    asm volatile("cp.async.cg.shared.global [%0], [%1], 16;" :: "r"(dst), "l"(src));
}
__device__ __forceinline__ void cp_commit() { asm volatile("cp.async.commit_group;"); }
template<int N> __device__ __forceinline__ void cp_wait() {
    asm volatile("cp.async.wait_group %0;" :: "n"(N));
}
__device__ __forceinline__ void ldsm_x4t(unsigned& d0, unsigned& d1,
                                         unsigned& d2, unsigned& d3, uint32_t addr) {
    asm volatile("ldmatrix.sync.aligned.m8n8.x4.trans.shared.b16 {%0,%1,%2,%3}, [%4];"
                 : "=r"(d0), "=r"(d1), "=r"(d2), "=r"(d3) : "r"(addr));
}
__device__ __forceinline__ void ldsm_x4(unsigned& d0, unsigned& d1,
                                        unsigned& d2, unsigned& d3, uint32_t addr) {
    asm volatile("ldmatrix.sync.aligned.m8n8.x4.shared.b16 {%0,%1,%2,%3}, [%4];"
                 : "=r"(d0), "=r"(d1), "=r"(d2), "=r"(d3) : "r"(addr));
}

// ---------------- prep: fold BN(+scale) into QKV weights, convert out_w ----------------
__global__ void prep_k(const float* __restrict__ qkv_w, const float* __restrict__ qkv_b,
                       const float* __restrict__ gamma, const float* __restrict__ beta,
                       const float* __restrict__ mean,  const float* __restrict__ var,
                       const float* __restrict__ out_w) {
    if (blockIdx.x >= 768) {
        int i = (blockIdx.x - 768) * 256 + threadIdx.x;
        g_Woh[i] = __float2half(out_w[i]);
        return;
    }
    int o = blockIdx.x;
    int c = threadIdx.x;
    float sc = gamma[c] * rsqrtf(var[c] + EPSV);
    float sh = beta[c] - mean[c] * sc;
    float w = qkv_w[o * 256 + c];
    float qsc = ((o % 192) < 64) ? QSCALE : 1.f;
    g_Wh[o * 256 + c] = __float2half(w * sc * qsc);
    float part = w * sh;
    __shared__ float red[8];
    #pragma unroll
    for (int m = 16; m > 0; m >>= 1) part += __shfl_xor_sync(0xffffffffu, part, m);
    if ((c & 31) == 0) red[c >> 5] = part;
    __syncthreads();
    if (c < 8) {
        float v = red[c];
        #pragma unroll
        for (int m = 4; m > 0; m >>= 1) v += __shfl_xor_sync(0xffu, v, m);
        if (c == 0) g_bp[o] = (qkv_b[o] + v) * qsc;
    }
}

// ---------------- X-resident fp16 GEMM (unchanged from R9/R10) ----------------
#define GX_STR 136
#define GX_SZ  (256 * GX_STR)
#define GW_STG (128 * 40)
#define GH_SMEM_BYTES ((GX_SZ + 4 * GW_STG) * 2)

__global__ void __launch_bounds__(256, 2) gemm_h(const __half* __restrict__ W,
                                                 const float* __restrict__ bias,
                                                 const float* __restrict__ Xf,
                                                 const __half* __restrict__ Xh,
                                                 __half* __restrict__ Yh,
                                                 float* __restrict__ Yf,
                                                 const float* __restrict__ resid,
                                                 int M) {
    extern __shared__ __half sg[];
    __half* Xs = sg;
    uint32_t xsb = (uint32_t)__cvta_generic_to_shared(Xs);
    uint32_t wsb = xsb + (uint32_t)GX_SZ * 2;

    int tid = threadIdx.x;
    int w = tid >> 5, lane = tid & 31, r = lane >> 2, ql = lane & 3;
    int wm = w >> 1, wn = w & 1;
    int pbase = blockIdx.x * 128, b = blockIdx.z;
    const int L = M >> 8;
    const int NIT = 8 * L;

    int g = lane >> 3, jj = lane & 7;
    uint32_t x_rp = (uint32_t)((((g & 1) * 8 + jj) * GX_STR + (g >> 1) * 8) * 2);
    uint32_t w_rp = (uint32_t)(((lane & 15) * 40 + (lane >> 4) * 8) * 2);

    auto w_load = [&](int m) {
        int ob = (blockIdx.y * L + (m >> 3)) * 128;
        int kc = (m & 7) * 32;
        uint32_t sb = wsb + (uint32_t)((m & 3) * GW_STG) * 2;
        #pragma unroll
        for (int it = tid; it < 512; it += 256) {
            int o = it >> 2, f8 = it & 3;
            cp16(sb + (uint32_t)(o * 40 + f8 * 8) * 2,
                 W + (size_t)(ob + o) * 256 + kc + f8 * 8);
        }
    };

    if (Xf) {
        cp_commit();
        const float* Xb = Xf + (size_t)b * 256 * 1024;
        #pragma unroll 4
        for (int it = tid; it < 8192; it += 256) {
            int c = it >> 5, p4 = it & 31;
            float4 v = *(const float4*)&Xb[c * 1024 + pbase + p4 * 4];
            uint2 u = make_uint2(packh2(v.x, v.y), packh2(v.z, v.w));
            *(uint2*)&Xs[c * GX_STR + p4 * 4] = u;
        }
    } else {
        const __half* Xb = Xh + (size_t)b * 256 * 1024;
        #pragma unroll 4
        for (int it = tid; it < 4096; it += 256) {
            int c = it >> 4, f8 = it & 15;
            cp16(xsb + (uint32_t)(c * GX_STR + f8 * 8) * 2,
                 Xb + (size_t)c * 1024 + pbase + f8 * 8);
        }
        cp_commit();
    }
    w_load(0); cp_commit();
    w_load(1); cp_commit();
    w_load(2); cp_commit();

    float acc[2][8][4];
    #pragma unroll
    for (int t = 0; t < 2; t++)
        #pragma unroll
        for (int nb = 0; nb < 8; nb++)
            #pragma unroll
            for (int j = 0; j < 4; j++) acc[t][nb][j] = 0.f;

    const int orow = wm * 32, ncol = wn * 64;

    for (int m = 0; m < NIT; m++) {
        cp_wait<2>();
        __syncthreads();

        uint32_t sbc = wsb + (uint32_t)((m & 3) * GW_STG) * 2;
        int ki = m & 7;
        #pragma unroll
        for (int kk = 0; kk < 2; kk++) {
            unsigned a[2][4];
            #pragma unroll
            for (int t = 0; t < 2; t++)
                ldsm_x4(a[t][0], a[t][1], a[t][2], a[t][3],
                        sbc + (uint32_t)(((orow + t * 16) * 40 + kk * 16) * 2) + w_rp);
            #pragma unroll
            for (int nb2 = 0; nb2 < 8; nb2 += 2) {
                unsigned d0, d1, d2, d3;
                ldsm_x4t(d0, d1, d2, d3,
                         xsb + (uint32_t)(((ki * 32 + kk * 16) * GX_STR + ncol + nb2 * 8) * 2) + x_rp);
                mma_f16(acc[0][nb2],     a[0], d0, d1);
                mma_f16(acc[1][nb2],     a[1], d0, d1);
                mma_f16(acc[0][nb2 + 1], a[0], d2, d3);
                mma_f16(acc[1][nb2 + 1], a[1], d2, d3);
            }
        }

        if (m + 3 < NIT) w_load(m + 3);
        cp_commit();

        if (ki == 7) {
            int obase = (blockIdx.y * L + (m >> 3)) * 128;
            #pragma unroll
            for (int t = 0; t < 2; t++) {
                int o0 = obase + orow + t * 16 + r;
                float bv0 = bias[o0], bv1 = bias[o0 + 8];
                #pragma unroll
                for (int nb = 0; nb < 8; nb++) {
                    int col = pbase + ncol + nb * 8 + 2 * ql;
                    size_t i0 = ((size_t)b * M + o0) * 1024 + col;
                    size_t i1 = ((size_t)b * M + o0 + 8) * 1024 + col;
                    if (Yh) {
                        *(unsigned*)&Yh[i0] = packh2(acc[t][nb][0] + bv0, acc[t][nb][1] + bv0);
                        *(unsigned*)&Yh[i1] = packh2(acc[t][nb][2] + bv1, acc[t][nb][3] + bv1);
                    } else {
                        float2 r0 = *(const float2*)&resid[i0];
                        float2 r1 = *(const float2*)&resid[i1];
                        *(float2*)&Yf[i0] = make_float2(acc[t][nb][0] + bv0 + r0.x,
                                                        acc[t][nb][1] + bv0 + r0.y);
                        *(float2*)&Yf[i1] = make_float2(acc[t][nb][2] + bv1 + r1.x,
                                                        acc[t][nb][3] + bv1 + r1.y);
                    }
                    acc[t][nb][0] = acc[t][nb][1] = acc[t][nb][2] = acc[t][nb][3] = 0.f;
                }
            }
        }
    }
}

// ---------------- flash attention: 3 CTAs/SM (3-stage, shared ones, lean regs) ----------------
// q-tile 128, grid (8, 4, 16), block 128 (4 warps x 32 q-rows), 3 CTAs/SM.
#define FH_QSTR 136
#define FH_KSTR 72
#define FH_U (64 * FH_QSTR)          // 8704
#define FH_K (64 * FH_KSTR)          // 4608
#define FH_ONES (FH_U + 6 * FH_K)    // 36352
#define FH_SMEM_BYTES ((FH_ONES + 8 * FH_KSTR) * 2)   // 73856 B

__global__ void __launch_bounds__(128, 3) flash_h(const __half* __restrict__ qkv,
                                                  __half* __restrict__ av) {
    extern __shared__ __half sh[];
    __half* Us = sh;
    uint32_t usb = (uint32_t)__cvta_generic_to_shared(Us);

    int tid = threadIdx.x;
    int w = tid >> 5, lane = tid & 31, r = lane >> 2, ql = lane & 3;
    int qb = blockIdx.x * 128;
    int h  = blockIdx.y;
    int b  = blockIdx.z;

    const size_t hb = ((size_t)b * 768 + (size_t)h * 192) * 1024;
    const __half* Qg = qkv + hb;
    const __half* Kg = qkv + hb + 64 * 1024;
    const __half* Vg = qkv + hb + 128 * 1024;

    // shared static ones block (row 0 = ones, rows 1-7 = zeros)
    for (int idx = tid; idx < 8 * FH_KSTR; idx += 128)
        sh[FH_ONES + idx] = __ushort_as_half((unsigned short)((idx < FH_KSTR) ? 0x3C00 : 0));

    auto kbuf = [&](int s) { return usb + (uint32_t)(FH_U + s * FH_K) * 2; };
    auto vbuf = [&](int s) { return usb + (uint32_t)(FH_U + (3 + s) * FH_K) * 2; };
    auto load_kv = [&](int s, int kbase) {
        uint32_t kb = kbuf(s), vb = vbuf(s);
        #pragma unroll
        for (int idx = tid; idx < 1024; idx += 128) {
            if (idx < 512) {
                int c = idx >> 3, f8 = idx & 7;
                cp16(kb + (uint32_t)(c * FH_KSTR + f8 * 8) * 2,
                     Kg + (size_t)c * 1024 + kbase + f8 * 8);
            } else {
                int j = idx - 512;
                int c = j >> 3, f8 = j & 7;
                cp16(vb + (uint32_t)(c * FH_KSTR + f8 * 8) * 2,
                     Vg + (size_t)c * 1024 + kbase + f8 * 8);
            }
        }
    };

    // prologue: Q (g0), KV tiles 0,1 (g1,g2)
    #pragma unroll
    for (int idx = tid; idx < 1024; idx += 128) {
        int c = idx >> 4, f8 = idx & 15;
        cp16(usb + (uint32_t)(c * FH_QSTR + f8 * 8) * 2, Qg + (size_t)c * 1024 + qb + f8 * 8);
    }
    cp_commit();
    load_kv(0, 0);   cp_commit();
    load_kv(1, 64);  cp_commit();

    int g = lane >> 3, jj = lane & 7;
    uint32_t q_rp = (uint32_t)((((g >> 1) * 8 + jj) * FH_QSTR + (g & 1) * 8) * 2);
    uint32_t k_rp = (uint32_t)((((g & 1) * 8 + jj) * FH_KSTR + (g >> 1) * 8) * 2);
    uint32_t v_rp = (uint32_t)((((g >> 1) * 8 + jj) * FH_KSTR + (g & 1) * 8) * 2);

    const int qrow = w * 32;
    float O[2][8][4], O9[2][4];
    #pragma unroll
    for (int t = 0; t < 2; t++) {
        #pragma unroll
        for (int nb = 0; nb < 8; nb++)
            #pragma unroll
            for (int j = 0; j < 4; j++) O[t][nb][j] = 0.f;
        #pragma unroll
        for (int j = 0; j < 4; j++) O9[t][j] = 0.f;
    }

    unsigned oc0 = 0, oc1 = 0;   // ones B-frag (loaded after first barrier)
    bool ones_loaded = false;

    for (int kt = 0; kt < 16; kt++) {
        cp_wait<1>();
        __syncthreads();
        if (!ones_loaded) {
            oc0 = *(const unsigned*)&sh[FH_ONES + r * FH_KSTR + 2 * ql];
            oc1 = *(const unsigned*)&sh[FH_ONES + r * FH_KSTR + 2 * ql + 8];
            ones_loaded = true;
        }

        int s = kt % 3;
        uint32_t kcur = kbuf(s);
        uint32_t vcur = vbuf(s);

        #pragma unroll
        for (int t = 0; t < 2; t++) {
            int q0b = qrow + t * 16;

            // ---- S = Q K^T (Q frags via ldsm from stationary stage) ----
            float S[8][4];
            #pragma unroll
            for (int nb = 0; nb < 8; nb++)
                #pragma unroll
                for (int j = 0; j < 4; j++) S[nb][j] = 0.f;

            #pragma unroll
            for (int kk = 0; kk < 4; kk++) {
                unsigned qa[4];
                ldsm_x4t(qa[0], qa[1], qa[2], qa[3],
                         usb + (uint32_t)((kk * 16 * FH_QSTR + q0b) * 2) + q_rp);
                #pragma unroll
                for (int nb2 = 0; nb2 < 8; nb2 += 2) {
                    unsigned d0, d1, d2, d3;
                    ldsm_x4t(d0, d1, d2, d3,
                             kcur + (uint32_t)((kk * 16 * FH_KSTR + nb2 * 8) * 2) + k_rp);
                    mma_f16(S[nb2],     qa, d0, d1);
                    mma_f16(S[nb2 + 1], qa, d2, d3);
                }
            }

            // ---- P = exp2(S) in f16x2 ----
            unsigned pa[4][4];
            #pragma unroll
            for (int kk = 0; kk < 4; kk++) {
                pa[kk][0] = h2exp2(packh2(S[2 * kk][0],     S[2 * kk][1]));
                pa[kk][1] = h2exp2(packh2(S[2 * kk][2],     S[2 * kk][3]));
                pa[kk][2] = h2exp2(packh2(S[2 * kk + 1][0], S[2 * kk + 1][1]));
                pa[kk][3] = h2exp2(packh2(S[2 * kk + 1][2], S[2 * kk + 1][3]));
            }

            // ---- O += P V ----
            #pragma unroll
            for (int kk = 0; kk < 4; kk++) {
                #pragma unroll
                for (int nb2 = 0; nb2 < 8; nb2 += 2) {
                    unsigned e0, e1, e2, e3;
                    ldsm_x4(e0, e1, e2, e3,
                            vcur + (uint32_t)((nb2 * 8 * FH_KSTR + kk * 16) * 2) + v_rp);
                    mma_f16(O[t][nb2],     pa[kk], e0, e1);
                    mma_f16(O[t][nb2 + 1], pa[kk], e2, e3);
                }
            }
            // ---- row-sum: O9 += presum(P) . ones ----
            unsigned ps[4];
            #pragma unroll
            for (int j = 0; j < 4; j++)
                ps[j] = h2add(h2add(pa[0][j], pa[1][j]), h2add(pa[2][j], pa[3][j]));
            mma_f16(O9[t], ps, oc0, oc1);
        }

        if (kt + 2 < 16) load_kv((kt + 2) % 3, (kt + 2) * 64);
        cp_commit();
    }

    // ---- l from O9 col 0 (lane ql=0) ----
    unsigned short* Uw = (unsigned short*)Us;
    __syncthreads();   // all warps done with Q stage before overwrite
    #pragma unroll
    for (int t = 0; t < 2; t++) {
        float l0 = __shfl_sync(0xffffffffu, O9[t][0], lane & 28);
        float l1 = __shfl_sync(0xffffffffu, O9[t][2], lane & 28);
        float inv0 = 1.f / l0, inv1 = 1.f / l1;
        int q0 = qrow + t * 16 + r;
        #pragma unroll
        for (int nb = 0; nb < 8; nb++) {
            int c = nb * 8 + 2 * ql;
            Uw[c * FH_QSTR + q0]           = __half_as_ushort(__float2half(O[t][nb][0] * inv0));
            Uw[(c + 1) * FH_QSTR + q0]     = __half_as_ushort(__float2half(O[t][nb][1] * inv0));
            Uw[c * FH_QSTR + q0 + 8]       = __half_as_ushort(__float2half(O[t][nb][2] * inv1));
            Uw[(c + 1) * FH_QSTR + q0 + 8] = __half_as_ushort(__float2half(O[t][nb][3] * inv1));
        }
    }
    __syncthreads();

    size_t ob = ((size_t)b * 256 + (size_t)h * 64) * 1024 + qb;
    for (int idx = tid; idx < 64 * 64; idx += 128) {
        int c = idx >> 6, wd = idx & 63;
        *(unsigned*)&av[ob + (size_t)c * 1024 + wd * 2] = ((unsigned*)Us)[c * (FH_QSTR / 2) + wd];
    }
}

// ---------------- launcher ----------------
extern "C" void kernel_launch(void* const* d_in, const int* in_sizes, int n_in,
                              void* d_out, int out_size) {
    const float* x      = (const float*)d_in[0];
    const float* gamma  = (const float*)d_in[1];
    const float* beta   = (const float*)d_in[2];
    const float* rmean  = (const float*)d_in[3];
    const float* rvar   = (const float*)d_in[4];
    const float* qkv_w  = (const float*)d_in[5];
    const float* qkv_b  = (const float*)d_in[6];
    const float* out_w  = (const float*)d_in[7];
    const float* out_b  = (const float*)d_in[8];

    float* bp;
    __half *Wh, *Woh, *qkvh, *avh;
    cudaGetSymbolAddress((void**)&Wh,   g_Wh);
    cudaGetSymbolAddress((void**)&bp,   g_bp);
    cudaGetSymbolAddress((void**)&Woh,  g_Woh);
    cudaGetSymbolAddress((void**)&qkvh, g_qkvh);
    cudaGetSymbolAddress((void**)&avh,  g_avh);

    cudaFuncSetAttribute(gemm_h,  cudaFuncAttributeMaxDynamicSharedMemorySize, GH_SMEM_BYTES);
    cudaFuncSetAttribute(flash_h, cudaFuncAttributeMaxDynamicSharedMemorySize, FH_SMEM_BYTES);

    prep_k<<<1024, 256>>>(qkv_w, qkv_b, gamma, beta, rmean, rvar, out_w);
    gemm_h<<<dim3(8, 2, 16), 256, GH_SMEM_BYTES>>>(Wh, bp, x, nullptr, qkvh, nullptr, nullptr, 768);
    flash_h<<<dim3(8, 4, 16), 128, FH_SMEM_BYTES>>>(qkvh, avh);
    gemm_h<<<dim3(8, 2, 16), 256, GH_SMEM_BYTES>>>(Woh, out_b, nullptr, avh, nullptr, (float*)d_out, x, 256);
}

// round 12
// speedup vs baseline: 1.0835x; 1.0835x over previous
#include <cuda_runtime.h>
#include <cuda_fp16.h>
#include <cuda.h>
#include <cstdint>

#define EPSV 1e-5f
#define QSCALE (0.0625f * 1.44269504088896340736f)   // 1/sqrt(256) * log2(e)

// ---------------- scratch ----------------
__device__ __half g_Wh[768 * 256];
__device__ float  g_bp[768];
__device__ __half g_Woh[256 * 256];
__device__ __half g_qkvh[16 * 768 * 1024];   // [b][o][p] fp16
__device__ __half g_avh[16 * 256 * 1024];    // [b][c][p] fp16

// ---------------- helpers ----------------
__device__ __forceinline__ void mma_f16(float c[4], const unsigned a[4],
                                        unsigned b0, unsigned b1) {
    asm volatile("mma.sync.aligned.m16n8k16.row.col.f32.f16.f16.f32 "
                 "{%0,%1,%2,%3}, {%4,%5,%6,%7}, {%8,%9}, {%0,%1,%2,%3};"
                 : "+f"(c[0]), "+f"(c[1]), "+f"(c[2]), "+f"(c[3])
                 : "r"(a[0]), "r"(a[1]), "r"(a[2]), "r"(a[3]), "r"(b0), "r"(b1));
}
__device__ __forceinline__ unsigned packh2(float lo, float hi) {
    unsigned d; asm("cvt.rn.f16x2.f32 %0, %1, %2;" : "=r"(d) : "f"(hi), "f"(lo)); return d;
}
__device__ __forceinline__ unsigned h2exp2(unsigned x) {
    unsigned r; asm("ex2.approx.f16x2 %0, %1;" : "=r"(r) : "r"(x)); return r;
}
__device__ __forceinline__ unsigned h2add(unsigned a, unsigned b) {
    unsigned r; asm("add.f16x2 %0, %1, %2;" : "=r"(r) : "r"(a), "r"(b)); return r;
}
__device__ __forceinline__ void cp16(uint32_t dst, const void* src) {
    asm volatile("cp.async.cg.shared.global [%0], [%1], 16;" :: "r"(dst), "l"(src));
}
__device__ __forceinline__ void cp_commit() { asm volatile("cp.async.commit_group;"); }
template<int N> __device__ __forceinline__ void cp_wait() {
    asm volatile("cp.async.wait_group %0;" :: "n"(N));
}
__device__ __forceinline__ void ldsm_x4t(unsigned& d0, unsigned& d1,
                                         unsigned& d2, unsigned& d3, uint32_t addr) {
    asm volatile("ldmatrix.sync.aligned.m8n8.x4.trans.shared.b16 {%0,%1,%2,%3}, [%4];"
                 : "=r"(d0), "=r"(d1), "=r"(d2), "=r"(d3) : "r"(addr));
}
__device__ __forceinline__ void ldsm_x4(unsigned& d0, unsigned& d1,
                                        unsigned& d2, unsigned& d3, uint32_t addr) {
    asm volatile("ldmatrix.sync.aligned.m8n8.x4.shared.b16 {%0,%1,%2,%3}, [%4];"
                 : "=r"(d0), "=r"(d1), "=r"(d2), "=r"(d3) : "r"(addr));
}
__device__ __forceinline__ void mbar_init(uint32_t a, unsigned cnt) {
    asm volatile("mbarrier.init.shared.b64 [%0], %1;" :: "r"(a), "r"(cnt) : "memory");
}
__device__ __forceinline__ void mbar_expect(uint32_t a, unsigned bytes) {
    asm volatile("mbarrier.arrive.expect_tx.shared.b64 _, [%0], %1;" :: "r"(a), "r"(bytes) : "memory");
}
__device__ __forceinline__ void mbar_wait(uint32_t a, unsigned par) {
    unsigned done;
    asm volatile("{\n\t.reg .pred p;\n\t"
                 "mbarrier.try_wait.parity.acquire.cta.shared::cta.b64 p, [%1], %2;\n\t"
                 "selp.b32 %0, 1, 0, p;\n\t}" : "=r"(done) : "r"(a), "r"(par) : "memory");
    if (!done) {
        asm volatile("{\n\t.reg .pred P1;\n\t"
                     "WL%=:\n\t"
                     "mbarrier.try_wait.parity.acquire.cta.shared::cta.b64 P1, [%0], %1, 0x989680;\n\t"
                     "@P1 bra.uni WD%=;\n\t"
                     "bra.uni WL%=;\n\t"
                     "WD%=:\n\t}" :: "r"(a), "r"(par) : "memory");
    }
}
__device__ __forceinline__ void tma3d(uint32_t dst, const void* map,
                                      int x, int y, int z, uint32_t mbar) {
    asm volatile("cp.async.bulk.tensor.3d.shared::cta.global.tile.mbarrier::complete_tx::bytes "
                 "[%0], [%1, {%2, %3, %4}], [%5];"
                 :: "r"(dst), "l"(map), "r"(x), "r"(y), "r"(z), "r"(mbar) : "memory");
}

// ---------------- prep ----------------
__global__ void prep_k(const float* __restrict__ qkv_w, const float* __restrict__ qkv_b,
                       const float* __restrict__ gamma, const float* __restrict__ beta,
                       const float* __restrict__ mean,  const float* __restrict__ var,
                       const float* __restrict__ out_w) {
    if (blockIdx.x >= 768) {
        int i = (blockIdx.x - 768) * 256 + threadIdx.x;
        g_Woh[i] = __float2half(out_w[i]);
        return;
    }
    int o = blockIdx.x;
    int c = threadIdx.x;
    float sc = gamma[c] * rsqrtf(var[c] + EPSV);
    float sh = beta[c] - mean[c] * sc;
    float w = qkv_w[o * 256 + c];
    float qsc = ((o % 192) < 64) ? QSCALE : 1.f;
    g_Wh[o * 256 + c] = __float2half(w * sc * qsc);
    float part = w * sh;
    __shared__ float red[8];
    #pragma unroll
    for (int m = 16; m > 0; m >>= 1) part += __shfl_xor_sync(0xffffffffu, part, m);
    if ((c & 31) == 0) red[c >> 5] = part;
    __syncthreads();
    if (c < 8) {
        float v = red[c];
        #pragma unroll
        for (int m = 4; m > 0; m >>= 1) v += __shfl_xor_sync(0xffu, v, m);
        if (c == 0) g_bp[o] = (qkv_b[o] + v) * qsc;
    }
}

// ---------------- X-resident fp16 GEMM (unchanged, best known) ----------------
#define GX_STR 136
#define GX_SZ  (256 * GX_STR)
#define GW_STG (128 * 40)
#define GH_SMEM_BYTES ((GX_SZ + 4 * GW_STG) * 2)

__global__ void __launch_bounds__(256, 2) gemm_h(const __half* __restrict__ W,
                                                 const float* __restrict__ bias,
                                                 const float* __restrict__ Xf,
                                                 const __half* __restrict__ Xh,
                                                 __half* __restrict__ Yh,
                                                 float* __restrict__ Yf,
                                                 const float* __restrict__ resid,
                                                 int M) {
    extern __shared__ __half sg[];
    __half* Xs = sg;
    uint32_t xsb = (uint32_t)__cvta_generic_to_shared(Xs);
    uint32_t wsb = xsb + (uint32_t)GX_SZ * 2;

    int tid = threadIdx.x;
    int w = tid >> 5, lane = tid & 31, r = lane >> 2, ql = lane & 3;
    int wm = w >> 1, wn = w & 1;
    int pbase = blockIdx.x * 128, b = blockIdx.z;
    const int L = M >> 8;
    const int NIT = 8 * L;

    int g = lane >> 3, jj = lane & 7;
    uint32_t x_rp = (uint32_t)((((g & 1) * 8 + jj) * GX_STR + (g >> 1) * 8) * 2);
    uint32_t w_rp = (uint32_t)(((lane & 15) * 40 + (lane >> 4) * 8) * 2);

    auto w_load = [&](int m) {
        int ob = (blockIdx.y * L + (m >> 3)) * 128;
        int kc = (m & 7) * 32;
        uint32_t sb = wsb + (uint32_t)((m & 3) * GW_STG) * 2;
        #pragma unroll
        for (int it = tid; it < 512; it += 256) {
            int o = it >> 2, f8 = it & 3;
            cp16(sb + (uint32_t)(o * 40 + f8 * 8) * 2,
                 W + (size_t)(ob + o) * 256 + kc + f8 * 8);
        }
    };

    if (Xf) {
        cp_commit();
        const float* Xb = Xf + (size_t)b * 256 * 1024;
        #pragma unroll 4
        for (int it = tid; it < 8192; it += 256) {
            int c = it >> 5, p4 = it & 31;
            float4 v = *(const float4*)&Xb[c * 1024 + pbase + p4 * 4];
            uint2 u = make_uint2(packh2(v.x, v.y), packh2(v.z, v.w));
            *(uint2*)&Xs[c * GX_STR + p4 * 4] = u;
        }
    } else {
        const __half* Xb = Xh + (size_t)b * 256 * 1024;
        #pragma unroll 4
        for (int it = tid; it < 4096; it += 256) {
            int c = it >> 4, f8 = it & 15;
            cp16(xsb + (uint32_t)(c * GX_STR + f8 * 8) * 2,
                 Xb + (size_t)c * 1024 + pbase + f8 * 8);
        }
        cp_commit();
    }
    w_load(0); cp_commit();
    w_load(1); cp_commit();
    w_load(2); cp_commit();

    float acc[2][8][4];
    #pragma unroll
    for (int t = 0; t < 2; t++)
        #pragma unroll
        for (int nb = 0; nb < 8; nb++)
            #pragma unroll
            for (int j = 0; j < 4; j++) acc[t][nb][j] = 0.f;

    const int orow = wm * 32, ncol = wn * 64;

    for (int m = 0; m < NIT; m++) {
        cp_wait<2>();
        __syncthreads();

        uint32_t sbc = wsb + (uint32_t)((m & 3) * GW_STG) * 2;
        int ki = m & 7;
        #pragma unroll
        for (int kk = 0; kk < 2; kk++) {
            unsigned a[2][4];
            #pragma unroll
            for (int t = 0; t < 2; t++)
                ldsm_x4(a[t][0], a[t][1], a[t][2], a[t][3],
                        sbc + (uint32_t)(((orow + t * 16) * 40 + kk * 16) * 2) + w_rp);
            #pragma unroll
            for (int nb2 = 0; nb2 < 8; nb2 += 2) {
                unsigned d0, d1, d2, d3;
                ldsm_x4t(d0, d1, d2, d3,
                         xsb + (uint32_t)(((ki * 32 + kk * 16) * GX_STR + ncol + nb2 * 8) * 2) + x_rp);
                mma_f16(acc[0][nb2],     a[0], d0, d1);
                mma_f16(acc[1][nb2],     a[1], d0, d1);
                mma_f16(acc[0][nb2 + 1], a[0], d2, d3);
                mma_f16(acc[1][nb2 + 1], a[1], d2, d3);
            }
        }

        if (m + 3 < NIT) w_load(m + 3);
        cp_commit();

        if (ki == 7) {
            int obase = (blockIdx.y * L + (m >> 3)) * 128;
            #pragma unroll
            for (int t = 0; t < 2; t++) {
                int o0 = obase + orow + t * 16 + r;
                float bv0 = bias[o0], bv1 = bias[o0 + 8];
                #pragma unroll
                for (int nb = 0; nb < 8; nb++) {
                    int col = pbase + ncol + nb * 8 + 2 * ql;
                    size_t i0 = ((size_t)b * M + o0) * 1024 + col;
                    size_t i1 = ((size_t)b * M + o0 + 8) * 1024 + col;
                    if (Yh) {
                        *(unsigned*)&Yh[i0] = packh2(acc[t][nb][0] + bv0, acc[t][nb][1] + bv0);
                        *(unsigned*)&Yh[i1] = packh2(acc[t][nb][2] + bv1, acc[t][nb][3] + bv1);
                    } else {
                        float2 r0 = *(const float2*)&resid[i0];
                        float2 r1 = *(const float2*)&resid[i1];
                        *(float2*)&Yf[i0] = make_float2(acc[t][nb][0] + bv0 + r0.x,
                                                        acc[t][nb][1] + bv0 + r0.y);
                        *(float2*)&Yf[i1] = make_float2(acc[t][nb][2] + bv1 + r1.x,
                                                        acc[t][nb][3] + bv1 + r1.y);
                    }
                    acc[t][nb][0] = acc[t][nb][1] = acc[t][nb][2] = acc[t][nb][3] = 0.f;
                }
            }
        }
    }
}

// ---------------- flash attention: TMA K/V (SW128), warp-M 32, block 128, 2 CTAs/SM ----------------
// q-tile 128, grid (8, 4, 16). KV stages at 1024-aligned base:
// stage s: K @ s*16384 (64 rows x 128B, SW128), V @ s*16384+8192.
// Q stage (cp.async, stride 136) @ +49152; ones @ +66560; mbars @ +67712.
#define FT_STAGE 16384
#define FT_QOFF  49152
#define FT_QSTR  136
#define FT_ONES  66560
#define FT_MBAR  67712
#define FH_SMEM_BYTES (67744 + 1024)

__global__ void __launch_bounds__(128, 2) flash_h(const __half* __restrict__ qkv,
                                                  __half* __restrict__ av,
                                                  const __grid_constant__ CUtensorMap tmap) {
    extern __shared__ __half sh[];
    uint32_t usb = (uint32_t)__cvta_generic_to_shared(sh);
    uint32_t kvb = (usb + 1023u) & ~1023u;
    __half* shA = (__half*)((char*)sh + (kvb - usb));

    int tid = threadIdx.x;
    int w = tid >> 5, lane = tid & 31, r = lane >> 2, ql = lane & 3;
    int qb = blockIdx.x * 128;
    int h  = blockIdx.y;
    int b  = blockIdx.z;

    const size_t hb = ((size_t)b * 768 + (size_t)h * 192) * 1024;
    const __half* Qg = qkv + hb;
    const int yK = h * 192 + 64;     // K channel rows in tensormap dim1
    const int yV = h * 192 + 128;    // V channel rows

    // mbar init (tid 0)
    if (tid == 0) {
        #pragma unroll
        for (int s = 0; s < 3; s++) mbar_init(kvb + FT_MBAR + s * 8, 1);
    }
    // ones block (8 rows x 72 halves; row 0 ones)
    __half* shO = shA + FT_ONES / 2;
    for (int idx = tid; idx < 8 * 72; idx += 128)
        shO[idx] = __ushort_as_half((unsigned short)((idx < 72) ? 0x3C00 : 0));
    // Q stage cp.async
    uint32_t qsb = kvb + FT_QOFF;
    #pragma unroll
    for (int idx = tid; idx < 1024; idx += 128) {
        int c = idx >> 4, f8 = idx & 15;
        cp16(qsb + (uint32_t)(c * FT_QSTR + f8 * 8) * 2, Qg + (size_t)c * 1024 + qb + f8 * 8);
    }
    cp_commit();
    __syncthreads();   // mbars + ones visible

    if (tid == 0) {
        asm volatile("fence.proxy.async.shared::cta;" ::: "memory");
        #pragma unroll
        for (int s = 0; s < 2; s++) {
            uint32_t mb = kvb + FT_MBAR + s * 8;
            mbar_expect(mb, 2 * FT_STAGE / 2);
            tma3d(kvb + s * FT_STAGE,        &tmap, s * 64, yK, b, mb);
            tma3d(kvb + s * FT_STAGE + 8192, &tmap, s * 64, yV, b, mb);
        }
    }

    cp_wait<0>();
    __syncthreads();   // Q staged

    // Q fragments (persistent, one-time)
    const int qrow = w * 32;
    const unsigned short* Uss = (const unsigned short*)(shA + FT_QOFF / 2);
    unsigned qf[2][4][4];
    #pragma unroll
    for (int t = 0; t < 2; t++)
        #pragma unroll
        for (int kk = 0; kk < 4; kk++) {
            int q0 = qrow + t * 16 + r;
            int c0 = kk * 16 + 2 * ql;
            qf[t][kk][0] = (unsigned)Uss[c0 * FT_QSTR + q0]           | ((unsigned)Uss[(c0 + 1) * FT_QSTR + q0] << 16);
            qf[t][kk][1] = (unsigned)Uss[c0 * FT_QSTR + q0 + 8]       | ((unsigned)Uss[(c0 + 1) * FT_QSTR + q0 + 8] << 16);
            qf[t][kk][2] = (unsigned)Uss[(c0 + 8) * FT_QSTR + q0]     | ((unsigned)Uss[(c0 + 9) * FT_QSTR + q0] << 16);
            qf[t][kk][3] = (unsigned)Uss[(c0 + 8) * FT_QSTR + q0 + 8] | ((unsigned)Uss[(c0 + 9) * FT_QSTR + q0 + 8] << 16);
        }

    int g = lane >> 3, jj = lane & 7;
    int g1 = g & 1, g2 = g >> 1;
    uint32_t rbK = (uint32_t)((g1 * 8 + jj) * 128);   // K row base (channel row)
    uint32_t rbV = (uint32_t)((g2 * 8 + jj) * 128);   // V row base (out-channel row)
    unsigned oc0 = *(const unsigned*)&shO[r * 72 + 2 * ql];
    unsigned oc1 = *(const unsigned*)&shO[r * 72 + 2 * ql + 8];

    float O[2][8][4], O9[2][4];
    #pragma unroll
    for (int t = 0; t < 2; t++) {
        #pragma unroll
        for (int nb = 0; nb < 8; nb++)
            #pragma unroll
            for (int j = 0; j < 4; j++) O[t][nb][j] = 0.f;
        #pragma unroll
        for (int j = 0; j < 4; j++) O9[t][j] = 0.f;
    }

    for (int kt = 0; kt < 16; kt++) {
        int s = kt % 3;
        mbar_wait(kvb + FT_MBAR + s * 8, (unsigned)((kt / 3) & 1));
        __syncthreads();   // all done with tile kt-1's stage before refill

        if (tid == 0 && kt + 2 < 16) {
            int s2 = (kt + 2) % 3;
            uint32_t mb = kvb + FT_MBAR + s2 * 8;
            mbar_expect(mb, FT_STAGE);
            tma3d(kvb + s2 * FT_STAGE,        &tmap, (kt + 2) * 64, yK, b, mb);
            tma3d(kvb + s2 * FT_STAGE + 8192, &tmap, (kt + 2) * 64, yV, b, mb);
        }

        uint32_t kcur = kvb + s * FT_STAGE;
        uint32_t vcur = kcur + 8192;

        #pragma unroll
        for (int t = 0; t < 2; t++) {
            // ---- S = Q K^T (SW128-swizzled ldsm) ----
            float S[8][4];
            #pragma unroll
            for (int nb = 0; nb < 8; nb++)
                #pragma unroll
                for (int j = 0; j < 4; j++) S[nb][j] = 0.f;

            #pragma unroll
            for (int kk = 0; kk < 4; kk++) {
                #pragma unroll
                for (int nb2 = 0; nb2 < 8; nb2 += 2) {
                    unsigned d0, d1, d2, d3;
                    ldsm_x4t(d0, d1, d2, d3,
                             kcur + (uint32_t)(kk * 2048) + rbK
                                  + ((uint32_t)((nb2 + g2) ^ jj) << 4));
                    mma_f16(S[nb2],     qf[t][kk], d0, d1);
                    mma_f16(S[nb2 + 1], qf[t][kk], d2, d3);
                }
            }

            // ---- P = exp2(S) in f16x2 ----
            unsigned pa[4][4];
            #pragma unroll
            for (int kk = 0; kk < 4; kk++) {
                pa[kk][0] = h2exp2(packh2(S[2 * kk][0],     S[2 * kk][1]));
                pa[kk][1] = h2exp2(packh2(S[2 * kk][2],     S[2 * kk][3]));
                pa[kk][2] = h2exp2(packh2(S[2 * kk + 1][0], S[2 * kk + 1][1]));
                pa[kk][3] = h2exp2(packh2(S[2 * kk + 1][2], S[2 * kk + 1][3]));
            }

            // ---- O += P V (SW128-swizzled ldsm) ----
            #pragma unroll
            for (int kk = 0; kk < 4; kk++) {
                #pragma unroll
                for (int nb2 = 0; nb2 < 8; nb2 += 2) {
                    unsigned e0, e1, e2, e3;
                    ldsm_x4(e0, e1, e2, e3,
                            vcur + (uint32_t)(nb2 * 1024) + rbV
                                 + ((uint32_t)((kk * 2 + g1) ^ jj) << 4));
                    mma_f16(O[t][nb2],     pa[kk], e0, e1);
                    mma_f16(O[t][nb2 + 1], pa[kk], e2, e3);
                }
            }
            // ---- row-sum ----
            unsigned ps[4];
            #pragma unroll
            for (int j = 0; j < 4; j++)
                ps[j] = h2add(h2add(pa[0][j], pa[1][j]), h2add(pa[2][j], pa[3][j]));
            mma_f16(O9[t], ps, oc0, oc1);
        }
    }

    // ---- finalize ----
    unsigned short* Uw = (unsigned short*)(shA + FT_QOFF / 2);
    #pragma unroll
    for (int t = 0; t < 2; t++) {
        float l0 = __shfl_sync(0xffffffffu, O9[t][0], lane & 28);
        float l1 = __shfl_sync(0xffffffffu, O9[t][2], lane & 28);
        float inv0 = 1.f / l0, inv1 = 1.f / l1;
        int q0 = qrow + t * 16 + r;
        #pragma unroll
        for (int nb = 0; nb < 8; nb++) {
            int c = nb * 8 + 2 * ql;
            Uw[c * FT_QSTR + q0]           = __half_as_ushort(__float2half(O[t][nb][0] * inv0));
            Uw[(c + 1) * FT_QSTR + q0]     = __half_as_ushort(__float2half(O[t][nb][1] * inv0));
            Uw[c * FT_QSTR + q0 + 8]       = __half_as_ushort(__float2half(O[t][nb][2] * inv1));
            Uw[(c + 1) * FT_QSTR + q0 + 8] = __half_as_ushort(__float2half(O[t][nb][3] * inv1));
        }
    }
    __syncthreads();

    size_t ob = ((size_t)b * 256 + (size_t)h * 64) * 1024 + qb;
    for (int idx = tid; idx < 64 * 64; idx += 128) {
        int c = idx >> 6, wd = idx & 63;
        *(unsigned*)&av[ob + (size_t)c * 1024 + wd * 2] =
            ((unsigned*)(shA + FT_QOFF / 2))[c * (FT_QSTR / 2) + wd];
    }
}

// ---------------- launcher ----------------
extern "C" void kernel_launch(void* const* d_in, const int* in_sizes, int n_in,
                              void* d_out, int out_size) {
    const float* x      = (const float*)d_in[0];
    const float* gamma  = (const float*)d_in[1];
    const float* beta   = (const float*)d_in[2];
    const float* rmean  = (const float*)d_in[3];
    const float* rvar   = (const float*)d_in[4];
    const float* qkv_w  = (const float*)d_in[5];
    const float* qkv_b  = (const float*)d_in[6];
    const float* out_w  = (const float*)d_in[7];
    const float* out_b  = (const float*)d_in[8];

    float* bp;
    __half *Wh, *Woh, *qkvh, *avh;
    cudaGetSymbolAddress((void**)&Wh,   g_Wh);
    cudaGetSymbolAddress((void**)&bp,   g_bp);
    cudaGetSymbolAddress((void**)&Woh,  g_Woh);
    cudaGetSymbolAddress((void**)&qkvh, g_qkvh);
    cudaGetSymbolAddress((void**)&avh,  g_avh);

    // tensormap over qkvh: dims {p=1024, o=768, b=16}, box {64, 64, 1}, SW128
    static CUtensorMap tmap;
    {
        typedef CUresult (*EncFn)(CUtensorMap*, CUtensorMapDataType, cuuint32_t, void*,
                                  const cuuint64_t*, const cuuint64_t*, const cuuint32_t*,
                                  const cuuint32_t*, CUtensorMapInterleave, CUtensorMapSwizzle,
                                  CUtensorMapL2promotion, CUtensorMapFloatOOBfill);
        static EncFn enc = nullptr;
        if (!enc) {
            void* fn = nullptr;
            cudaDriverEntryPointQueryResult qr;
            cudaGetDriverEntryPointByVersion("cuTensorMapEncodeTiled", &fn, 12000,
                                             cudaEnableDefault, &qr);
            enc = (EncFn)fn;
        }
        cuuint64_t dims[3]    = {1024, 768, 16};
        cuuint64_t strides[2] = {2048, 768ull * 2048ull};
        cuuint32_t box[3]     = {64, 64, 1};
        cuuint32_t estr[3]    = {1, 1, 1};
        enc(&tmap, CU_TENSOR_MAP_DATA_TYPE_UINT16, 3, qkvh, dims, strides, box, estr,
            CU_TENSOR_MAP_INTERLEAVE_NONE, CU_TENSOR_MAP_SWIZZLE_128B,
            CU_TENSOR_MAP_L2_PROMOTION_L2_128B, CU_TENSOR_MAP_FLOAT_OOB_FILL_NONE);
    }

    cudaFuncSetAttribute(gemm_h,  cudaFuncAttributeMaxDynamicSharedMemorySize, GH_SMEM_BYTES);
    cudaFuncSetAttribute(flash_h, cudaFuncAttributeMaxDynamicSharedMemorySize, FH_SMEM_BYTES);

    prep_k<<<1024, 256>>>(qkv_w, qkv_b, gamma, beta, rmean, rvar, out_w);
    gemm_h<<<dim3(8, 2, 16), 256, GH_SMEM_BYTES>>>(Wh, bp, x, nullptr, qkvh, nullptr, nullptr, 768);
    flash_h<<<dim3(8, 4, 16), 128, FH_SMEM_BYTES>>>(qkvh, avh, tmap);
    gemm_h<<<dim3(8, 2, 16), 256, GH_SMEM_BYTES>>>(Woh, out_b, nullptr, avh, nullptr, (float*)d_out, x, 256);
}